// round 12
// baseline (speedup 1.0000x reference)
#include <cuda_runtime.h>
#include <mma.h>
#include <cstdint>

using namespace nvcuda;

// Problem constants (B=4,H=8,S=1024,D=64)
#define BH 32
#define S 1024
#define D 64
#define N_ELE (BH * S * S)          // 33554432 = 2^25
#define SHIFT 9                     // PINNED: SHIFT=12 causes atomic contention collapse
#define NB (1u << (31 - SHIFT))     // 4M buckets
#define QPITCH 129                  // qk 128-wide tile pitch (mod 32 == 1)
#define HBLK 4096                   // histogram scan chunks (1024 buckets each)
#define AVP 72                      // av smem pitch (multiple of 8 floats for wmma ldm)

// Static device scratch (allocation-free rule: __device__ globals only)
__device__ float    g_score[N_ELE];      // signed cosine scores, row-major [BH*S, S]
__device__ float    g_w[N_ELE];          // final weights
__device__ unsigned g_hist[NB];          // bucket populations
__device__ unsigned g_partial[HBLK];     // per-chunk population sums
__device__ float    g_wmag[NB];          // per-bucket weight magnitude
__device__ float    g_invr[BH * S];      // 1 / rowsum(|w|)
__device__ float    g_invq[BH * S];
__device__ float    g_invk[BH * S];

// ---------------------------------------------------------------------------
// Stage 1: inverse lengths (one warp per row) + fused histogram zeroing
// ---------------------------------------------------------------------------
__global__ void norms_zero_kernel(const float* __restrict__ q,
                                  const float* __restrict__ k) {
    unsigned gid = blockIdx.x * blockDim.x + threadIdx.x;
    if (gid < NB / 4)
        reinterpret_cast<uint4*>(g_hist)[gid] = make_uint4(0u, 0u, 0u, 0u);

    int warp = gid >> 5;
    int lane = threadIdx.x & 31;
    if (warp >= 2 * BH * S) return;
    bool is_q = warp < BH * S;
    int row = is_q ? warp : warp - BH * S;
    const float* p = (is_q ? q : k) + (size_t)row * D;
    float v0 = p[lane], v1 = p[lane + 32];
    float s = v0 * v0 + v1 * v1;
    #pragma unroll
    for (int o = 16; o; o >>= 1) s += __shfl_xor_sync(0xffffffffu, s, o);
    if (lane == 0) (is_q ? g_invq : g_invk)[row] = 1.0f / (sqrtf(s) + 1e-5f);
}

// ---------------------------------------------------------------------------
// Stage 2: QK^T (fp32) -> signed scores (STG.128) + atomic bucket histogram
// 128x128 tile, 256 threads, 8x8 micro-tile (proven core, unchanged)
// ---------------------------------------------------------------------------
__global__ void qk_kernel(const float* __restrict__ Q, const float* __restrict__ K) {
    extern __shared__ float sm[];
    float* Qs = sm;                    // [64][QPITCH]  Qs[d][r]
    float* Ks = sm + 64 * QPITCH;      // [64][QPITCH]  Ks[d][c]
    int bh = blockIdx.z;
    int i0 = blockIdx.y * 128;
    int j0 = blockIdx.x * 128;
    const float* Qb = Q + ((size_t)bh * S + i0) * D;
    const float* Kb = K + ((size_t)bh * S + j0) * D;
    int tid = threadIdx.x;

    #pragma unroll
    for (int l = 0; l < 32; l++) {
        int idx = tid + l * 256;          // 0..8191
        int r = idx >> 6, d = idx & 63;
        Qs[d * QPITCH + r] = Qb[(size_t)r * D + d];
        Ks[d * QPITCH + r] = Kb[(size_t)r * D + d];
    }
    __syncthreads();

    int tx = tid & 15, ty = tid >> 4;     // 16x16 threads, 8x8 each
    float acc[8][8] = {};
    #pragma unroll 8
    for (int d = 0; d < 64; d++) {
        float a[8], b[8];
        const float* Qrow = &Qs[d * QPITCH + ty * 8];
        const float* Krow = &Ks[d * QPITCH + tx * 8];
        #pragma unroll
        for (int u = 0; u < 8; u++) a[u] = Qrow[u];
        #pragma unroll
        for (int u = 0; u < 8; u++) b[u] = Krow[u];
        #pragma unroll
        for (int r = 0; r < 8; r++)
            #pragma unroll
            for (int u = 0; u < 8; u++)
                acc[r][u] += a[r] * b[u];
    }

    float iq[8], ik[8];
    #pragma unroll
    for (int u = 0; u < 8; u++) {
        iq[u] = g_invq[bh * S + i0 + ty * 8 + u];
        ik[u] = g_invk[bh * S + j0 + tx * 8 + u];
    }
    #pragma unroll
    for (int r = 0; r < 8; r++) {
        unsigned row = (unsigned)(bh * S + i0 + ty * 8 + r);
        float s[8];
        #pragma unroll
        for (int u = 0; u < 8; u++) s[u] = acc[r][u] * iq[r] * ik[u];
        unsigned base = (row << 10) | (unsigned)(j0 + tx * 8);
        *reinterpret_cast<float4*>(&g_score[base]) =
            make_float4(s[0], s[1], s[2], s[3]);
        *reinterpret_cast<float4*>(&g_score[base + 4]) =
            make_float4(s[4], s[5], s[6], s[7]);
        #pragma unroll
        for (int u = 0; u < 8; u++) {
            unsigned key = __float_as_uint(s[u]) & 0x7fffffffu;
            atomicAdd(&g_hist[key >> SHIFT], 1u);
        }
    }
}

// ---------------------------------------------------------------------------
// Stage 3a: per-chunk population sums (HBLK chunks of 1024 buckets)
// ---------------------------------------------------------------------------
__global__ void hist_sum_kernel() {
    __shared__ unsigned red[256];
    unsigned t = threadIdx.x, b = blockIdx.x;
    uint4 h = reinterpret_cast<const uint4*>(g_hist)[b * 256 + t];
    red[t] = h.x + h.y + h.z + h.w;
    __syncthreads();
    #pragma unroll
    for (int o = 128; o; o >>= 1) {
        if (t < (unsigned)o) red[t] += red[t + o];
        __syncthreads();
    }
    if (t == 0) g_partial[b] = red[0];
}

// ---------------------------------------------------------------------------
// Stage 3b: per-chunk offset + intra-chunk scan + wmag, one pass
// ---------------------------------------------------------------------------
__global__ void scan_wmag_kernel() {
    __shared__ unsigned red[256];
    __shared__ unsigned sscan[256];
    unsigned t = threadIdx.x, b = blockIdx.x;

    unsigned s = 0;
    for (unsigned i = t; i < b; i += 256) s += g_partial[i];
    red[t] = s;
    __syncthreads();
    #pragma unroll
    for (int o = 128; o; o >>= 1) {
        if (t < (unsigned)o) red[t] += red[t + o];
        __syncthreads();
    }
    unsigned blockoff = red[0];
    __syncthreads();

    uint4 h = reinterpret_cast<const uint4*>(g_hist)[b * 256 + t];
    unsigned s4 = h.x + h.y + h.z + h.w;
    unsigned v = s4;
    sscan[t] = v;
    __syncthreads();
    #pragma unroll
    for (int o = 1; o < 256; o <<= 1) {
        unsigned add = (t >= (unsigned)o) ? sscan[t - o] : 0u;
        __syncthreads();
        v += add;
        sscan[t] = v;
        __syncthreads();
    }
    unsigned excl = blockoff + v - s4;

    unsigned pops[4] = {h.x, h.y, h.z, h.w};
    unsigned cums[4] = {excl, excl + h.x, excl + h.x + h.y,
                        excl + h.x + h.y + h.z};
    const float inv = 1.0f / (float)(N_ELE - 1);
    float w[4];
    #pragma unroll
    for (int u = 0; u < 4; u++) {
        if (pops[u] == 0u) { w[u] = 0.0f; continue; }
        float rmid = (float)cums[u] + 0.5f * (float)(pops[u] - 1u);
        w[u] = -logf(fmaf(rmid, inv, 0x1p-25f));
    }
    reinterpret_cast<float4*>(g_wmag)[b * 256 + t] =
        make_float4(w[0], w[1], w[2], w[3]);
}

// ---------------------------------------------------------------------------
// Stage 4: elementwise weights + per-row L1 sums
// One block per score row; w = sign(score)*wmag[bucket]; g_invr = 1/sum|w|
// ---------------------------------------------------------------------------
__global__ void weight_kernel() {
    __shared__ float red[256];
    unsigned row = blockIdx.x;
    unsigned t = threadIdx.x;
    unsigned i = row * (unsigned)S + t * 4u;
    float4 s4 = *reinterpret_cast<const float4*>(&g_score[i]);
    float sv[4] = {s4.x, s4.y, s4.z, s4.w};
    float w[4];
    float asum = 0.0f;
    #pragma unroll
    for (int u = 0; u < 4; u++) {
        unsigned key = __float_as_uint(sv[u]) & 0x7fffffffu;
        float m = (key == 0u) ? 0.0f : __ldg(&g_wmag[key >> SHIFT]);
        asum += m;
        w[u] = copysignf(m, sv[u]);
    }
    *reinterpret_cast<float4*>(&g_w[i]) = make_float4(w[0], w[1], w[2], w[3]);

    red[t] = asum;
    __syncthreads();
    #pragma unroll
    for (int o = 128; o >= 32; o >>= 1) {
        if (t < (unsigned)o) red[t] += red[t + o];
        __syncthreads();
    }
    if (t < 32) {
        float v = red[t];
        #pragma unroll
        for (int o = 16; o; o >>= 1) v += __shfl_xor_sync(0xffffffffu, v, o);
        if (t == 0) g_invr[row] = 1.0f / v;
    }
}

// ---------------------------------------------------------------------------
// Stage 5: out[i,:] = g_invr[i] * (W[i,:] @ V)   — tf32 tensor cores
// 64x64 output tile, 128 threads (4 warps), each warp: 16 rows x 64 cols,
// wmma m16n16k8 tf32 with fp32 accumulate. Smem pitch 72 (wmma ldm-aligned).
// ---------------------------------------------------------------------------
__global__ void __launch_bounds__(128)
av_kernel(const float* __restrict__ V, float* __restrict__ out) {
    __shared__ float Ws[64][AVP];   // Ws[r][kk]  (also reused for output)
    __shared__ float Vs[64][AVP];   // Vs[kk][c]
    int bh = blockIdx.y;
    int i0 = blockIdx.x * 64;
    int tid = threadIdx.x;
    int warp = tid >> 5;
    const float* Wb = g_w + ((size_t)(bh * S + i0)) * S;
    const float* Vb = V + (size_t)bh * S * D;

    wmma::fragment<wmma::accumulator, 16, 16, 8, float> acc[4];
    #pragma unroll
    for (int n = 0; n < 4; n++) wmma::fill_fragment(acc[n], 0.0f);

    for (int kt = 0; kt < S; kt += 64) {
        #pragma unroll
        for (int l = 0; l < 8; l++) {
            int idx = tid + l * 128;           // 0..1023 float4 slots
            int r = idx >> 4, c = (idx & 15) * 4;
            *reinterpret_cast<float4*>(&Ws[r][c]) =
                *reinterpret_cast<const float4*>(&Wb[(size_t)r * S + kt + c]);
            *reinterpret_cast<float4*>(&Vs[r][c]) =
                *reinterpret_cast<const float4*>(&Vb[(size_t)(kt + r) * D + c]);
        }
        __syncthreads();
        #pragma unroll
        for (int k0 = 0; k0 < 64; k0 += 8) {
            wmma::fragment<wmma::matrix_a, 16, 16, 8,
                           wmma::precision::tf32, wmma::row_major> af;
            wmma::load_matrix_sync(af, &Ws[warp * 16][k0], AVP);
            #pragma unroll
            for (int t = 0; t < af.num_elements; t++)
                af.x[t] = wmma::__float_to_tf32(af.x[t]);
            #pragma unroll
            for (int n = 0; n < 4; n++) {
                wmma::fragment<wmma::matrix_b, 16, 16, 8,
                               wmma::precision::tf32, wmma::row_major> bf;
                wmma::load_matrix_sync(bf, &Vs[k0][n * 16], AVP);
                #pragma unroll
                for (int t = 0; t < bf.num_elements; t++)
                    bf.x[t] = wmma::__float_to_tf32(bf.x[t]);
                wmma::mma_sync(acc[n], af, bf, acc[n]);
            }
        }
        __syncthreads();
    }

    // dump accumulators into Ws (each warp owns rows [16w,16w+16) — disjoint)
    #pragma unroll
    for (int n = 0; n < 4; n++)
        wmma::store_matrix_sync(&Ws[warp * 16][n * 16], acc[n], AVP,
                                wmma::mem_row_major);
    __syncthreads();

    // scale by 1/rowsum and write out
    #pragma unroll
    for (int l = 0; l < 8; l++) {
        int idx = tid + l * 128;
        int r = idx >> 4, c = (idx & 15) * 4;
        int row = bh * S + i0 + r;
        float inv = g_invr[row];
        float4 o = *reinterpret_cast<float4*>(&Ws[r][c]);
        *reinterpret_cast<float4*>(&out[(size_t)row * D + c]) =
            make_float4(o.x * inv, o.y * inv, o.z * inv, o.w * inv);
    }
}

// ---------------------------------------------------------------------------
extern "C" void kernel_launch(void* const* d_in, const int* in_sizes, int n_in,
                              void* d_out, int out_size) {
    const float* q = (const float*)d_in[0];
    const float* k = (const float*)d_in[1];
    const float* v = (const float*)d_in[2];
    float* out = (float*)d_out;

    // Stage 1: inverse lengths + zero histogram (fused)
    norms_zero_kernel<<<8192, 256>>>(q, k);

    // Stage 2: cosine scores + bucket histogram (128x128 tiles, 66KB dyn smem)
    const int qk_smem = 2 * 64 * QPITCH * sizeof(float);
    cudaFuncSetAttribute(qk_kernel, cudaFuncAttributeMaxDynamicSharedMemorySize,
                         qk_smem);
    dim3 g1(S / 128, S / 128, BH);
    qk_kernel<<<g1, 256, qk_smem>>>(q, k);

    // Stage 3: custom scan + wmag
    hist_sum_kernel<<<HBLK, 256>>>();
    scan_wmag_kernel<<<HBLK, 256>>>();

    // Stage 4: weights + per-row L1 sums (one block per row)
    weight_kernel<<<BH * S, 256>>>();

    // Stage 5: tf32 tensor-core GEMM + scale by 1/rowsum
    dim3 g2(S / 64, BH);
    av_kernel<<<g2, 128>>>(v, out);
}

// round 16
// speedup vs baseline: 1.0208x; 1.0208x over previous
#include <cuda_runtime.h>
#include <cstdint>

// Problem constants (B=4,H=8,S=1024,D=64)
#define BH 32
#define S 1024
#define D 64
#define N_ELE (BH * S * S)          // 33554432 = 2^25
#define SHIFT 9                     // histogram buckets (PINNED: coarser collapses atomics)
#define NB (1u << (31 - SHIFT))     // 4M fine buckets
#define SHIFT2 17                   // lookup-table buckets (64 per octave)
#define NT (1u << (31 - SHIFT2))    // 16384 table entries
#define FRACMASK 0x1FFFFu
#define FRACSCALE (1.0f / 131072.0f)
#define QPITCH 129                  // qk 128-wide tile pitch (mod 32 == 1)
#define HBLK 4096                   // histogram scan chunks (1024 buckets each)
#define AVP 68                      // av smem pitch (16B-aligned rows)

// Static device scratch (allocation-free rule: __device__ globals only)
__device__ float    g_score[N_ELE];      // signed cosine scores, row-major [BH*S, S]
__device__ float    g_w[N_ELE];          // final weights
__device__ unsigned g_hist[NB];          // fine-bucket populations
__device__ unsigned g_cum[NB];           // exclusive scan of populations
__device__ unsigned g_partial[HBLK];     // per-chunk population sums
__device__ float2   g_table[NT];         // (w_edge[cb], w_edge[cb+1]) pairs
__device__ float    g_invr[BH * S];      // 1 / rowsum(|w|)
__device__ float    g_invq[BH * S];
__device__ float    g_invk[BH * S];

// ---------------------------------------------------------------------------
// Stage 1: inverse lengths (one warp per row) + fused histogram zeroing
// ---------------------------------------------------------------------------
__global__ void norms_zero_kernel(const float* __restrict__ q,
                                  const float* __restrict__ k) {
    unsigned gid = blockIdx.x * blockDim.x + threadIdx.x;
    if (gid < NB / 4)
        reinterpret_cast<uint4*>(g_hist)[gid] = make_uint4(0u, 0u, 0u, 0u);

    int warp = gid >> 5;
    int lane = threadIdx.x & 31;
    if (warp >= 2 * BH * S) return;
    bool is_q = warp < BH * S;
    int row = is_q ? warp : warp - BH * S;
    const float* p = (is_q ? q : k) + (size_t)row * D;
    float v0 = p[lane], v1 = p[lane + 32];
    float s = v0 * v0 + v1 * v1;
    #pragma unroll
    for (int o = 16; o; o >>= 1) s += __shfl_xor_sync(0xffffffffu, s, o);
    if (lane == 0) (is_q ? g_invq : g_invk)[row] = 1.0f / (sqrtf(s) + 1e-5f);
}

// ---------------------------------------------------------------------------
// Stage 2: QK^T (fp32 SIMT) -> signed scores (STG.128) + atomic histogram
// 128x128 tile, 256 threads, 8x8 micro-tile (proven core, unchanged)
// ---------------------------------------------------------------------------
__global__ void qk_kernel(const float* __restrict__ Q, const float* __restrict__ K) {
    extern __shared__ float sm[];
    float* Qs = sm;                    // [64][QPITCH]  Qs[d][r]
    float* Ks = sm + 64 * QPITCH;      // [64][QPITCH]  Ks[d][c]
    int bh = blockIdx.z;
    int i0 = blockIdx.y * 128;
    int j0 = blockIdx.x * 128;
    const float* Qb = Q + ((size_t)bh * S + i0) * D;
    const float* Kb = K + ((size_t)bh * S + j0) * D;
    int tid = threadIdx.x;

    #pragma unroll
    for (int l = 0; l < 32; l++) {
        int idx = tid + l * 256;          // 0..8191
        int r = idx >> 6, d = idx & 63;
        Qs[d * QPITCH + r] = Qb[(size_t)r * D + d];
        Ks[d * QPITCH + r] = Kb[(size_t)r * D + d];
    }
    __syncthreads();

    int tx = tid & 15, ty = tid >> 4;     // 16x16 threads, 8x8 each
    float acc[8][8] = {};
    #pragma unroll 8
    for (int d = 0; d < 64; d++) {
        float a[8], b[8];
        const float* Qrow = &Qs[d * QPITCH + ty * 8];
        const float* Krow = &Ks[d * QPITCH + tx * 8];
        #pragma unroll
        for (int u = 0; u < 8; u++) a[u] = Qrow[u];
        #pragma unroll
        for (int u = 0; u < 8; u++) b[u] = Krow[u];
        #pragma unroll
        for (int r = 0; r < 8; r++)
            #pragma unroll
            for (int u = 0; u < 8; u++)
                acc[r][u] += a[r] * b[u];
    }

    float iq[8], ik[8];
    #pragma unroll
    for (int u = 0; u < 8; u++) {
        iq[u] = g_invq[bh * S + i0 + ty * 8 + u];
        ik[u] = g_invk[bh * S + j0 + tx * 8 + u];
    }
    #pragma unroll
    for (int r = 0; r < 8; r++) {
        unsigned row = (unsigned)(bh * S + i0 + ty * 8 + r);
        float s[8];
        #pragma unroll
        for (int u = 0; u < 8; u++) s[u] = acc[r][u] * iq[r] * ik[u];
        unsigned base = (row << 10) | (unsigned)(j0 + tx * 8);
        *reinterpret_cast<float4*>(&g_score[base]) =
            make_float4(s[0], s[1], s[2], s[3]);
        *reinterpret_cast<float4*>(&g_score[base + 4]) =
            make_float4(s[4], s[5], s[6], s[7]);
        #pragma unroll
        for (int u = 0; u < 8; u++) {
            unsigned key = __float_as_uint(s[u]) & 0x7fffffffu;
            atomicAdd(&g_hist[key >> SHIFT], 1u);
        }
    }
}

// ---------------------------------------------------------------------------
// Stage 3a: per-chunk population sums (HBLK chunks of 1024 buckets)
// ---------------------------------------------------------------------------
__global__ void hist_sum_kernel() {
    __shared__ unsigned red[256];
    unsigned t = threadIdx.x, b = blockIdx.x;
    uint4 h = reinterpret_cast<const uint4*>(g_hist)[b * 256 + t];
    red[t] = h.x + h.y + h.z + h.w;
    __syncthreads();
    #pragma unroll
    for (int o = 128; o; o >>= 1) {
        if (t < (unsigned)o) red[t] += red[t + o];
        __syncthreads();
    }
    if (t == 0) g_partial[b] = red[0];
}

// ---------------------------------------------------------------------------
// Stage 3b: per-chunk offset + intra-chunk scan -> exclusive cum, one pass
// ---------------------------------------------------------------------------
__global__ void scan_cum_kernel() {
    __shared__ unsigned red[256];
    __shared__ unsigned sscan[256];
    unsigned t = threadIdx.x, b = blockIdx.x;

    unsigned s = 0;
    for (unsigned i = t; i < b; i += 256) s += g_partial[i];
    red[t] = s;
    __syncthreads();
    #pragma unroll
    for (int o = 128; o; o >>= 1) {
        if (t < (unsigned)o) red[t] += red[t + o];
        __syncthreads();
    }
    unsigned blockoff = red[0];
    __syncthreads();

    uint4 h = reinterpret_cast<const uint4*>(g_hist)[b * 256 + t];
    unsigned s4 = h.x + h.y + h.z + h.w;
    unsigned v = s4;
    sscan[t] = v;
    __syncthreads();
    #pragma unroll
    for (int o = 1; o < 256; o <<= 1) {
        unsigned add = (t >= (unsigned)o) ? sscan[t - o] : 0u;
        __syncthreads();
        v += add;
        sscan[t] = v;
        __syncthreads();
    }
    unsigned excl = blockoff + v - s4;

    reinterpret_cast<uint4*>(g_cum)[b * 256 + t] =
        make_uint4(excl, excl + h.x, excl + h.x + h.y, excl + h.x + h.y + h.z);
}

// ---------------------------------------------------------------------------
// Stage 3c: build the piecewise-linear weight table.
// table[cb] = ( w(cum at fine edge cb*256), w(cum at fine edge (cb+1)*256) )
// w(c) = -log(c/(n-1) + 1/n)
// ---------------------------------------------------------------------------
__global__ void table_kernel() {
    unsigned cb = blockIdx.x * blockDim.x + threadIdx.x;   // 0..NT-1
    const float inv = 1.0f / (float)(N_ELE - 1);
    unsigned f0 = cb << (SHIFT2 - SHIFT);                  // cb*256
    unsigned f1 = f0 + (1u << (SHIFT2 - SHIFT));
    unsigned c0 = g_cum[f0];
    unsigned c1 = (f1 < NB) ? g_cum[f1] : (unsigned)N_ELE;
    float w0 = -logf(fmaf((float)c0, inv, 0x1p-25f));
    float w1 = -logf(fmaf((float)c1, inv, 0x1p-25f));
    g_table[cb] = make_float2(w0, w1);
}

// ---------------------------------------------------------------------------
// Stage 4: elementwise weights + per-row L1 sums.
// w = sign(score) * lerp(table[key>>SHIFT2], frac(key)); L1-resident table.
// One block per score row; g_invr[row] = 1/sum(|w|).
// ---------------------------------------------------------------------------
__global__ void weight_kernel() {
    __shared__ float red[256];
    unsigned row = blockIdx.x;
    unsigned t = threadIdx.x;
    unsigned i = row * (unsigned)S + t * 4u;
    float4 s4 = *reinterpret_cast<const float4*>(&g_score[i]);
    float sv[4] = {s4.x, s4.y, s4.z, s4.w};
    float w[4];
    float asum = 0.0f;
    #pragma unroll
    for (int u = 0; u < 4; u++) {
        unsigned key = __float_as_uint(sv[u]) & 0x7fffffffu;
        float m;
        if (key == 0u) {
            m = 0.0f;
        } else {
            float2 tb = __ldg(&g_table[key >> SHIFT2]);
            float frac = (float)(key & FRACMASK) * FRACSCALE;
            m = fmaf(frac, tb.y - tb.x, tb.x);
        }
        asum += m;
        w[u] = copysignf(m, sv[u]);
    }
    *reinterpret_cast<float4*>(&g_w[i]) = make_float4(w[0], w[1], w[2], w[3]);

    red[t] = asum;
    __syncthreads();
    #pragma unroll
    for (int o = 128; o >= 32; o >>= 1) {
        if (t < (unsigned)o) red[t] += red[t + o];
        __syncthreads();
    }
    if (t < 32) {
        float v = red[t];
        #pragma unroll
        for (int o = 16; o; o >>= 1) v += __shfl_xor_sync(0xffffffffu, v, o);
        if (t == 0) g_invr[row] = 1.0f / v;
    }
}

// ---------------------------------------------------------------------------
// Stage 5: out[i,:] = g_invr[i] * (W[i,:] @ V)  — proven R11 fp32 kernel
// ---------------------------------------------------------------------------
__global__ void av_kernel(const float* __restrict__ V, float* __restrict__ out) {
    __shared__ float Ws[64][AVP];   // Ws[r][kk]
    __shared__ float Vs[64][AVP];   // Vs[kk][c]
    int bh = blockIdx.y;
    int i0 = blockIdx.x * 64;
    int tid = threadIdx.x, tx = tid & 15, ty = tid >> 4;
    const float* Wb = g_w + ((size_t)(bh * S + i0)) * S;
    const float* Vb = V + (size_t)bh * S * D;

    float acc[4][4] = {};
    for (int kt = 0; kt < S; kt += 64) {
        #pragma unroll
        for (int l = 0; l < 4; l++) {
            int idx = tid + l * 256;           // 0..1023 float4 slots
            int r = idx >> 4, c = (idx & 15) * 4;
            *reinterpret_cast<float4*>(&Ws[r][c]) =
                *reinterpret_cast<const float4*>(&Wb[(size_t)r * S + kt + c]);
            *reinterpret_cast<float4*>(&Vs[r][c]) =
                *reinterpret_cast<const float4*>(&Vb[(size_t)(kt + r) * D + c]);
        }
        __syncthreads();
        #pragma unroll 8
        for (int kk = 0; kk < 64; kk++) {
            float4 b4 = *reinterpret_cast<const float4*>(&Vs[kk][tx * 4]);
            float b[4] = {b4.x, b4.y, b4.z, b4.w};
            float a[4];
            #pragma unroll
            for (int r = 0; r < 4; r++) a[r] = Ws[ty * 4 + r][kk];
            #pragma unroll
            for (int r = 0; r < 4; r++)
                #pragma unroll
                for (int u = 0; u < 4; u++)
                    acc[r][u] += a[r] * b[u];
        }
        __syncthreads();
    }
    #pragma unroll
    for (int r = 0; r < 4; r++) {
        int row = bh * S + i0 + ty * 4 + r;
        float inv = g_invr[row];
        *reinterpret_cast<float4*>(&out[(size_t)row * D + tx * 4]) =
            make_float4(acc[r][0] * inv, acc[r][1] * inv,
                        acc[r][2] * inv, acc[r][3] * inv);
    }
}

// ---------------------------------------------------------------------------
extern "C" void kernel_launch(void* const* d_in, const int* in_sizes, int n_in,
                              void* d_out, int out_size) {
    const float* q = (const float*)d_in[0];
    const float* k = (const float*)d_in[1];
    const float* v = (const float*)d_in[2];
    float* out = (float*)d_out;

    // Stage 1: inverse lengths + zero histogram (fused)
    norms_zero_kernel<<<8192, 256>>>(q, k);

    // Stage 2: fp32 scores + bucket histogram (128x128 tiles, 66KB dyn smem)
    const int qk_smem = 2 * 64 * QPITCH * sizeof(float);
    cudaFuncSetAttribute(qk_kernel, cudaFuncAttributeMaxDynamicSharedMemorySize,
                         qk_smem);
    dim3 g1(S / 128, S / 128, BH);
    qk_kernel<<<g1, 256, qk_smem>>>(q, k);

    // Stage 3: scan -> cum -> interpolation table
    hist_sum_kernel<<<HBLK, 256>>>();
    scan_cum_kernel<<<HBLK, 256>>>();
    table_kernel<<<NT / 256, 256>>>();

    // Stage 4: weights + per-row L1 sums (L1-resident lerp table)
    weight_kernel<<<BH * S, 256>>>();

    // Stage 5: GEMM + scale by 1/rowsum (proven R11 fp32)
    dim3 g2(S / 64, BH);
    av_kernel<<<g2, 256>>>(v, out);
}

// round 17
// speedup vs baseline: 1.0677x; 1.0459x over previous
#include <cuda_runtime.h>
#include <cstdint>

// Problem constants (B=4,H=8,S=1024,D=64)
#define BH 32
#define S 1024
#define D 64
#define N_ELE (BH * S * S)          // 33554432 = 2^25
#define SHIFT 9                     // histogram buckets (PINNED)
#define NB (1u << (31 - SHIFT))     // 4M fine buckets
#define SHIFT2 17                   // lookup-table buckets (64 per octave)
#define NT (1u << (31 - SHIFT2))    // 16384 table entries
#define FRACMASK 0x1FFFFu
#define FRACSCALE (1.0f / 131072.0f)
#define QPITCH 129                  // qk 128-wide tile pitch (mod 32 == 1)
#define HBLK 4096                   // histogram scan chunks (1024 buckets each)
#define AVP 68                      // av smem pitch (16B-aligned rows)

// Static device scratch (allocation-free rule: __device__ globals only)
__device__ float    g_score[N_ELE];      // signed cosine scores, row-major [BH*S, S]
__device__ unsigned g_hist[NB];          // fine-bucket populations
__device__ unsigned g_cum[NB];           // exclusive scan of populations
__device__ unsigned g_partial[HBLK];     // per-chunk population sums
__device__ float2   g_table[NT];         // (w_edge[cb], w_edge[cb+1]) pairs
__device__ float    g_invq[BH * S];
__device__ float    g_invk[BH * S];

// ---------------------------------------------------------------------------
// Stage 1: inverse lengths (one warp per row) + fused histogram zeroing
// ---------------------------------------------------------------------------
__global__ void norms_zero_kernel(const float* __restrict__ q,
                                  const float* __restrict__ k) {
    unsigned gid = blockIdx.x * blockDim.x + threadIdx.x;
    if (gid < NB / 4)
        reinterpret_cast<uint4*>(g_hist)[gid] = make_uint4(0u, 0u, 0u, 0u);

    int warp = gid >> 5;
    int lane = threadIdx.x & 31;
    if (warp >= 2 * BH * S) return;
    bool is_q = warp < BH * S;
    int row = is_q ? warp : warp - BH * S;
    const float* p = (is_q ? q : k) + (size_t)row * D;
    float v0 = p[lane], v1 = p[lane + 32];
    float s = v0 * v0 + v1 * v1;
    #pragma unroll
    for (int o = 16; o; o >>= 1) s += __shfl_xor_sync(0xffffffffu, s, o);
    if (lane == 0) (is_q ? g_invq : g_invk)[row] = 1.0f / (sqrtf(s) + 1e-5f);
}

// ---------------------------------------------------------------------------
// Stage 2: QK^T (fp32 SIMT) -> signed scores (STG.128) + atomic histogram
// 128x128 tile, 256 threads, 8x8 micro-tile (proven core, unchanged)
// ---------------------------------------------------------------------------
__global__ void qk_kernel(const float* __restrict__ Q, const float* __restrict__ K) {
    extern __shared__ float sm[];
    float* Qs = sm;                    // [64][QPITCH]  Qs[d][r]
    float* Ks = sm + 64 * QPITCH;      // [64][QPITCH]  Ks[d][c]
    int bh = blockIdx.z;
    int i0 = blockIdx.y * 128;
    int j0 = blockIdx.x * 128;
    const float* Qb = Q + ((size_t)bh * S + i0) * D;
    const float* Kb = K + ((size_t)bh * S + j0) * D;
    int tid = threadIdx.x;

    #pragma unroll
    for (int l = 0; l < 32; l++) {
        int idx = tid + l * 256;          // 0..8191
        int r = idx >> 6, d = idx & 63;
        Qs[d * QPITCH + r] = Qb[(size_t)r * D + d];
        Ks[d * QPITCH + r] = Kb[(size_t)r * D + d];
    }
    __syncthreads();

    int tx = tid & 15, ty = tid >> 4;     // 16x16 threads, 8x8 each
    float acc[8][8] = {};
    #pragma unroll 8
    for (int d = 0; d < 64; d++) {
        float a[8], b[8];
        const float* Qrow = &Qs[d * QPITCH + ty * 8];
        const float* Krow = &Ks[d * QPITCH + tx * 8];
        #pragma unroll
        for (int u = 0; u < 8; u++) a[u] = Qrow[u];
        #pragma unroll
        for (int u = 0; u < 8; u++) b[u] = Krow[u];
        #pragma unroll
        for (int r = 0; r < 8; r++)
            #pragma unroll
            for (int u = 0; u < 8; u++)
                acc[r][u] += a[r] * b[u];
    }

    float iq[8], ik[8];
    #pragma unroll
    for (int u = 0; u < 8; u++) {
        iq[u] = g_invq[bh * S + i0 + ty * 8 + u];
        ik[u] = g_invk[bh * S + j0 + tx * 8 + u];
    }
    #pragma unroll
    for (int r = 0; r < 8; r++) {
        unsigned row = (unsigned)(bh * S + i0 + ty * 8 + r);
        float s[8];
        #pragma unroll
        for (int u = 0; u < 8; u++) s[u] = acc[r][u] * iq[r] * ik[u];
        unsigned base = (row << 10) | (unsigned)(j0 + tx * 8);
        *reinterpret_cast<float4*>(&g_score[base]) =
            make_float4(s[0], s[1], s[2], s[3]);
        *reinterpret_cast<float4*>(&g_score[base + 4]) =
            make_float4(s[4], s[5], s[6], s[7]);
        #pragma unroll
        for (int u = 0; u < 8; u++) {
            unsigned key = __float_as_uint(s[u]) & 0x7fffffffu;
            atomicAdd(&g_hist[key >> SHIFT], 1u);
        }
    }
}

// ---------------------------------------------------------------------------
// Stage 3a: per-chunk population sums (HBLK chunks of 1024 buckets)
// ---------------------------------------------------------------------------
__global__ void hist_sum_kernel() {
    __shared__ unsigned red[256];
    unsigned t = threadIdx.x, b = blockIdx.x;
    uint4 h = reinterpret_cast<const uint4*>(g_hist)[b * 256 + t];
    red[t] = h.x + h.y + h.z + h.w;
    __syncthreads();
    #pragma unroll
    for (int o = 128; o; o >>= 1) {
        if (t < (unsigned)o) red[t] += red[t + o];
        __syncthreads();
    }
    if (t == 0) g_partial[b] = red[0];
}

// ---------------------------------------------------------------------------
// Stage 3b: per-chunk offset + intra-chunk scan -> exclusive cum, one pass
// ---------------------------------------------------------------------------
__global__ void scan_cum_kernel() {
    __shared__ unsigned red[256];
    __shared__ unsigned sscan[256];
    unsigned t = threadIdx.x, b = blockIdx.x;

    unsigned s = 0;
    for (unsigned i = t; i < b; i += 256) s += g_partial[i];
    red[t] = s;
    __syncthreads();
    #pragma unroll
    for (int o = 128; o; o >>= 1) {
        if (t < (unsigned)o) red[t] += red[t + o];
        __syncthreads();
    }
    unsigned blockoff = red[0];
    __syncthreads();

    uint4 h = reinterpret_cast<const uint4*>(g_hist)[b * 256 + t];
    unsigned s4 = h.x + h.y + h.z + h.w;
    unsigned v = s4;
    sscan[t] = v;
    __syncthreads();
    #pragma unroll
    for (int o = 1; o < 256; o <<= 1) {
        unsigned add = (t >= (unsigned)o) ? sscan[t - o] : 0u;
        __syncthreads();
        v += add;
        sscan[t] = v;
        __syncthreads();
    }
    unsigned excl = blockoff + v - s4;

    reinterpret_cast<uint4*>(g_cum)[b * 256 + t] =
        make_uint4(excl, excl + h.x, excl + h.x + h.y, excl + h.x + h.y + h.z);
}

// ---------------------------------------------------------------------------
// Stage 3c: build the piecewise-linear weight table.
// table[cb] = ( w(cum at fine edge cb*256), w(cum at fine edge (cb+1)*256) )
// ---------------------------------------------------------------------------
__global__ void table_kernel() {
    unsigned cb = blockIdx.x * blockDim.x + threadIdx.x;   // 0..NT-1
    const float inv = 1.0f / (float)(N_ELE - 1);
    unsigned f0 = cb << (SHIFT2 - SHIFT);                  // cb*256
    unsigned f1 = f0 + (1u << (SHIFT2 - SHIFT));
    unsigned c0 = g_cum[f0];
    unsigned c1 = (f1 < NB) ? g_cum[f1] : (unsigned)N_ELE;
    float w0 = -logf(fmaf((float)c0, inv, 0x1p-25f));
    float w1 = -logf(fmaf((float)c1, inv, 0x1p-25f));
    g_table[cb] = make_float2(w0, w1);
}

// ---------------------------------------------------------------------------
// Stage 4 (fused): out[i,:] = (W[i,:] @ V) / rowsum(|W[i,:]|)
// W materialized in the staging loop from g_score via the L1-resident lerp
// table; per-thread |w| partials accumulated across tiles, flushed to shared
// rsum once per block. 64x64 tile, 256 threads, 4x4 micro (R11 structure).
// ---------------------------------------------------------------------------
__global__ void av_kernel(const float* __restrict__ V, float* __restrict__ out) {
    __shared__ float Ws[64][AVP];   // Ws[r][kk]
    __shared__ float Vs[64][AVP];   // Vs[kk][c]
    __shared__ float rsum[64];
    int bh = blockIdx.y;
    int i0 = blockIdx.x * 64;
    int tid = threadIdx.x, tx = tid & 15, ty = tid >> 4;
    const float* Wb = g_score + ((size_t)(bh * S + i0)) * S;
    const float* Vb = V + (size_t)bh * S * D;

    if (tid < 64) rsum[tid] = 0.0f;
    float rs_part[4] = {0.0f, 0.0f, 0.0f, 0.0f};

    float acc[4][4] = {};
    for (int kt = 0; kt < S; kt += 64) {
        #pragma unroll
        for (int l = 0; l < 4; l++) {
            int idx = tid + l * 256;           // 0..1023 float4 slots
            int r = idx >> 4, c = (idx & 15) * 4;
            float4 s4 = *reinterpret_cast<const float4*>(&Wb[(size_t)r * S + kt + c]);
            float sv[4] = {s4.x, s4.y, s4.z, s4.w};
            float w[4];
            #pragma unroll
            for (int u = 0; u < 4; u++) {
                unsigned key = __float_as_uint(sv[u]) & 0x7fffffffu;
                float m;
                if (key == 0u) {
                    m = 0.0f;
                } else {
                    float2 tb = __ldg(&g_table[key >> SHIFT2]);
                    float frac = (float)(key & FRACMASK) * FRACSCALE;
                    m = fmaf(frac, tb.y - tb.x, tb.x);
                }
                rs_part[l] += m;
                w[u] = copysignf(m, sv[u]);
            }
            *reinterpret_cast<float4*>(&Ws[r][c]) =
                make_float4(w[0], w[1], w[2], w[3]);
            *reinterpret_cast<float4*>(&Vs[r][c]) =
                *reinterpret_cast<const float4*>(&Vb[(size_t)(kt + r) * D + c]);
        }
        __syncthreads();
        #pragma unroll 8
        for (int kk = 0; kk < 64; kk++) {
            float4 b4 = *reinterpret_cast<const float4*>(&Vs[kk][tx * 4]);
            float b[4] = {b4.x, b4.y, b4.z, b4.w};
            float a[4];
            #pragma unroll
            for (int r = 0; r < 4; r++) a[r] = Ws[ty * 4 + r][kk];
            #pragma unroll
            for (int r = 0; r < 4; r++)
                #pragma unroll
                for (int u = 0; u < 4; u++)
                    acc[r][u] += a[r] * b[u];
        }
        __syncthreads();
    }

    // flush per-thread |w| partials (thread's row for slot l is fixed)
    #pragma unroll
    for (int l = 0; l < 4; l++) {
        int r = (tid + l * 256) >> 4;
        atomicAdd(&rsum[r], rs_part[l]);
    }
    __syncthreads();

    #pragma unroll
    for (int r = 0; r < 4; r++) {
        int row = bh * S + i0 + ty * 4 + r;
        float inv = 1.0f / rsum[ty * 4 + r];
        *reinterpret_cast<float4*>(&out[(size_t)row * D + tx * 4]) =
            make_float4(acc[r][0] * inv, acc[r][1] * inv,
                        acc[r][2] * inv, acc[r][3] * inv);
    }
}

// ---------------------------------------------------------------------------
extern "C" void kernel_launch(void* const* d_in, const int* in_sizes, int n_in,
                              void* d_out, int out_size) {
    const float* q = (const float*)d_in[0];
    const float* k = (const float*)d_in[1];
    const float* v = (const float*)d_in[2];
    float* out = (float*)d_out;

    // Stage 1: inverse lengths + zero histogram (fused)
    norms_zero_kernel<<<8192, 256>>>(q, k);

    // Stage 2: fp32 scores + bucket histogram (128x128 tiles, 66KB dyn smem)
    const int qk_smem = 2 * 64 * QPITCH * sizeof(float);
    cudaFuncSetAttribute(qk_kernel, cudaFuncAttributeMaxDynamicSharedMemorySize,
                         qk_smem);
    dim3 g1(S / 128, S / 128, BH);
    qk_kernel<<<g1, 256, qk_smem>>>(q, k);

    // Stage 3: scan -> cum -> interpolation table
    hist_sum_kernel<<<HBLK, 256>>>();
    scan_cum_kernel<<<HBLK, 256>>>();
    table_kernel<<<NT / 256, 256>>>();

    // Stage 4 (fused): weights + rowsum + GEMM + normalize
    dim3 g2(S / 64, BH);
    av_kernel<<<g2, 256>>>(v, out);
}